// round 9
// baseline (speedup 1.0000x reference)
#include <cuda_runtime.h>
#include <cstdint>
#include <math.h>

#define S_  2048
#define B_  4
#define H_  2048
#define BS_ 8192
#define NEGV (-1e9f)
#define SCALE_ 0.17677669529663687f

typedef unsigned long long ull;

// ---------------- scratch (static __device__, no allocations) ----------------
__device__ __align__(128) float  g_Wcat[128 * H_];                 // 1 MB
__device__ __align__(128) float  g_proj[(size_t)BS_ * 128];        // 4 MB  [Qa|Ka|Qb|Kb]
__device__ __align__(128) float2 g_stats[(size_t)8 * S_];          // 128 KB {max, 1/sum}
__device__ __align__(128) float  g_hW1[(size_t)2 * BS_ * 128];     // 8 MB  h @ W1_{a,b}^T
__device__ __align__(128) float  g_part[(size_t)2 * 8 * S_ * 128]; // 16.8 MB split-K partials
__device__ __align__(128) float  g_Y [(size_t)2 * BS_ * 128];      // 8 MB  MLP hidden (gelu'd)

// ---------------- f32x2 packed FMA helpers (Blackwell FFMA2) ----------------
__device__ __forceinline__ ull pk(float lo, float hi) {
    ull r; asm("mov.b64 %0, {%1, %2};" : "=l"(r) : "f"(lo), "f"(hi)); return r;
}
__device__ __forceinline__ ull pk2(float v) {
    ull r; asm("mov.b64 %0, {%1, %1};" : "=l"(r) : "f"(v)); return r;
}
__device__ __forceinline__ void upk(ull v, float &lo, float &hi) {
    asm("mov.b64 {%0, %1}, %2;" : "=f"(lo), "=f"(hi) : "l"(v));
}
__device__ __forceinline__ void fma2(ull &d, ull a, ull b) {
    asm("fma.rn.f32x2 %0, %1, %2, %0;" : "+l"(d) : "l"(a), "l"(b));
}

__device__ __forceinline__ float gelu_exact(float x) {
    return 0.5f * x * (1.0f + erff(x * 0.7071067811865476f));
}

// ---------------- K0: pack the 4 attention projection weights ----------------
__global__ void pack_w(const float* __restrict__ qa, const float* __restrict__ ka,
                       const float* __restrict__ qb, const float* __restrict__ kb) {
    int i = blockIdx.x * blockDim.x + threadIdx.x;
    if (i >= 128 * H_) return;
    int c = i >> 11;
    int k = i & 2047;
    const float* src = (c < 32) ? qa + (size_t)c * H_
                     : (c < 64) ? ka + (size_t)(c - 32) * H_
                     : (c < 96) ? qb + (size_t)(c - 64) * H_
                                : kb + (size_t)(c - 96) * H_;
    g_Wcat[i] = src[k];
}

// ---------------- K1: fused projections, 128x128 tiles, double-buffered.
// grid (64, 3): y=0 proj=h@Wcat^T ; y=1 hW1_a=h@W1_a^T ; y=2 hW1_b=h@W1_b^T
__global__ void __launch_bounds__(256) gemm_h128v2(const float* __restrict__ h,
                                                   const float* __restrict__ W1a,
                                                   const float* __restrict__ W1b) {
    int sel = blockIdx.y;
    const float* W = (sel == 0) ? g_Wcat : (sel == 1) ? W1a : W1b;
    float* Out     = (sel == 0) ? g_proj : g_hW1 + (size_t)(sel - 1) * BS_ * 128;
    int r0 = blockIdx.x * 128;

    __shared__ float XsT[2][16][132];   // [k][m], m-contiguous (LDS.128 of m-quads)
    __shared__ float Ws [2][16][128];   // [k][c], n-pairs via LDS.64

    int tid = threadIdx.x;
    int tm = tid >> 4, tn = tid & 15;
    int lrow = tid & 127;               // loader: X row / W row
    int lk   = (tid >> 7) * 8;          // loader: k sub-offset (0 or 8)

    {   // initial tiles (k0 = 0)
        const float4* xp = (const float4*)(h + (size_t)(r0 + lrow) * H_ + lk);
        float4 x0 = xp[0], x1 = xp[1];
        XsT[0][lk + 0][lrow] = x0.x; XsT[0][lk + 1][lrow] = x0.y;
        XsT[0][lk + 2][lrow] = x0.z; XsT[0][lk + 3][lrow] = x0.w;
        XsT[0][lk + 4][lrow] = x1.x; XsT[0][lk + 5][lrow] = x1.y;
        XsT[0][lk + 6][lrow] = x1.z; XsT[0][lk + 7][lrow] = x1.w;
        const float4* wp = (const float4*)(W + (size_t)lrow * H_ + lk);
        float4 w0 = wp[0], w1 = wp[1];
        Ws[0][lk + 0][lrow] = w0.x; Ws[0][lk + 1][lrow] = w0.y;
        Ws[0][lk + 2][lrow] = w0.z; Ws[0][lk + 3][lrow] = w0.w;
        Ws[0][lk + 4][lrow] = w1.x; Ws[0][lk + 5][lrow] = w1.y;
        Ws[0][lk + 6][lrow] = w1.z; Ws[0][lk + 7][lrow] = w1.w;
    }
    __syncthreads();

    ull acc2[8][4];
    #pragma unroll
    for (int i = 0; i < 8; i++)
        #pragma unroll
        for (int j = 0; j < 4; j++) acc2[i][j] = 0ULL;

    for (int k0 = 0; k0 < H_; k0 += 16) {
        int buf = (k0 >> 4) & 1;
        bool hasNext = (k0 + 16) < H_;
        float4 nx0, nx1, nw0, nw1;
        if (hasNext) {
            const float4* xp = (const float4*)(h + (size_t)(r0 + lrow) * H_ + k0 + 16 + lk);
            nx0 = xp[0]; nx1 = xp[1];
            const float4* wp = (const float4*)(W + (size_t)lrow * H_ + k0 + 16 + lk);
            nw0 = wp[0]; nw1 = wp[1];
        }
        #pragma unroll
        for (int kk = 0; kk < 16; kk++) {
            const ull* b64 = (const ull*)&Ws[buf][kk][tn * 8];
            ull bb0 = b64[0], bb1 = b64[1], bb2 = b64[2], bb3 = b64[3];
            float4 av0 = *(const float4*)&XsT[buf][kk][tm * 8];
            float4 av1 = *(const float4*)&XsT[buf][kk][tm * 8 + 4];
            ull a2_0 = pk2(av0.x), a2_1 = pk2(av0.y), a2_2 = pk2(av0.z), a2_3 = pk2(av0.w);
            ull a2_4 = pk2(av1.x), a2_5 = pk2(av1.y), a2_6 = pk2(av1.z), a2_7 = pk2(av1.w);
            fma2(acc2[0][0], a2_0, bb0); fma2(acc2[0][1], a2_0, bb1); fma2(acc2[0][2], a2_0, bb2); fma2(acc2[0][3], a2_0, bb3);
            fma2(acc2[1][0], a2_1, bb0); fma2(acc2[1][1], a2_1, bb1); fma2(acc2[1][2], a2_1, bb2); fma2(acc2[1][3], a2_1, bb3);
            fma2(acc2[2][0], a2_2, bb0); fma2(acc2[2][1], a2_2, bb1); fma2(acc2[2][2], a2_2, bb2); fma2(acc2[2][3], a2_2, bb3);
            fma2(acc2[3][0], a2_3, bb0); fma2(acc2[3][1], a2_3, bb1); fma2(acc2[3][2], a2_3, bb2); fma2(acc2[3][3], a2_3, bb3);
            fma2(acc2[4][0], a2_4, bb0); fma2(acc2[4][1], a2_4, bb1); fma2(acc2[4][2], a2_4, bb2); fma2(acc2[4][3], a2_4, bb3);
            fma2(acc2[5][0], a2_5, bb0); fma2(acc2[5][1], a2_5, bb1); fma2(acc2[5][2], a2_5, bb2); fma2(acc2[5][3], a2_5, bb3);
            fma2(acc2[6][0], a2_6, bb0); fma2(acc2[6][1], a2_6, bb1); fma2(acc2[6][2], a2_6, bb2); fma2(acc2[6][3], a2_6, bb3);
            fma2(acc2[7][0], a2_7, bb0); fma2(acc2[7][1], a2_7, bb1); fma2(acc2[7][2], a2_7, bb2); fma2(acc2[7][3], a2_7, bb3);
        }
        if (hasNext) {
            int nbuf = buf ^ 1;
            XsT[nbuf][lk + 0][lrow] = nx0.x; XsT[nbuf][lk + 1][lrow] = nx0.y;
            XsT[nbuf][lk + 2][lrow] = nx0.z; XsT[nbuf][lk + 3][lrow] = nx0.w;
            XsT[nbuf][lk + 4][lrow] = nx1.x; XsT[nbuf][lk + 5][lrow] = nx1.y;
            XsT[nbuf][lk + 6][lrow] = nx1.z; XsT[nbuf][lk + 7][lrow] = nx1.w;
            Ws[nbuf][lk + 0][lrow] = nw0.x; Ws[nbuf][lk + 1][lrow] = nw0.y;
            Ws[nbuf][lk + 2][lrow] = nw0.z; Ws[nbuf][lk + 3][lrow] = nw0.w;
            Ws[nbuf][lk + 4][lrow] = nw1.x; Ws[nbuf][lk + 5][lrow] = nw1.y;
            Ws[nbuf][lk + 6][lrow] = nw1.z; Ws[nbuf][lk + 7][lrow] = nw1.w;
        }
        __syncthreads();
    }

    #pragma unroll
    for (int i = 0; i < 8; i++) {
        int row = r0 + tm * 8 + i;
        float c0, c1, c2, c3, c4, c5, c6, c7;
        upk(acc2[i][0], c0, c1); upk(acc2[i][1], c2, c3);
        upk(acc2[i][2], c4, c5); upk(acc2[i][3], c6, c7);
        *(float4*)(Out + (size_t)row * 128 + tn * 8)     = make_float4(c0, c1, c2, c3);
        *(float4*)(Out + (size_t)row * 128 + tn * 8 + 4) = make_float4(c4, c5, c6, c7);
    }
}

// ---------------- K2: per-row softmax stats (max, 1/sumexp) ------------------
__global__ void __launch_bounds__(256) softmax_stats(const int* __restrict__ mask) {
    int z = blockIdx.y, a = z >> 2, bb = z & 3;
    int s0 = blockIdx.x * 32;
    int tid = threadIdx.x, lane = tid & 31, w = tid >> 5;

    __shared__ float Qs[32][33];
    __shared__ float Ks[32][33];
    {
        int row = tid >> 3, j = (tid & 7) * 4;
        float4 v = *(const float4*)(g_proj + (size_t)(bb * S_ + s0 + row) * 128 + a * 64 + j);
        Qs[row][j] = v.x; Qs[row][j + 1] = v.y; Qs[row][j + 2] = v.z; Qs[row][j + 3] = v.w;
    }

    int tmax = s0 + 31;
    float mreg[4] = {NEGV, NEGV, NEGV, NEGV};

    for (int t0 = 0; t0 <= tmax; t0 += 32) {
        __syncthreads();
        {   int row = tid >> 3, j = (tid & 7) * 4;
            float4 v = *(const float4*)(g_proj + (size_t)(bb * S_ + t0 + row) * 128 + a * 64 + 32 + j);
            Ks[row][j] = v.x; Ks[row][j + 1] = v.y; Ks[row][j + 2] = v.z; Ks[row][j + 3] = v.w;
        }
        __syncthreads();
        int t = t0 + lane;
        int mv = mask[bb * S_ + t];
        #pragma unroll
        for (int rr = 0; rr < 4; rr++) {
            int sl = w * 4 + rr, s = s0 + sl;
            float dot = 0.0f;
            #pragma unroll
            for (int j = 0; j < 32; j++) dot += Qs[sl][j] * Ks[lane][j];
            float x = (t <= s && mv) ? dot * SCALE_ : NEGV;
            mreg[rr] = fmaxf(mreg[rr], x);
        }
    }
    float mfin[4];
    #pragma unroll
    for (int rr = 0; rr < 4; rr++) {
        float m = mreg[rr];
        #pragma unroll
        for (int off = 16; off > 0; off >>= 1)
            m = fmaxf(m, __shfl_xor_sync(0xffffffffu, m, off));
        mfin[rr] = m;
    }

    float lreg[4] = {0.f, 0.f, 0.f, 0.f};
    for (int t0 = 0; t0 <= tmax; t0 += 32) {
        __syncthreads();
        {   int row = tid >> 3, j = (tid & 7) * 4;
            float4 v = *(const float4*)(g_proj + (size_t)(bb * S_ + t0 + row) * 128 + a * 64 + 32 + j);
            Ks[row][j] = v.x; Ks[row][j + 1] = v.y; Ks[row][j + 2] = v.z; Ks[row][j + 3] = v.w;
        }
        __syncthreads();
        int t = t0 + lane;
        int mv = mask[bb * S_ + t];
        #pragma unroll
        for (int rr = 0; rr < 4; rr++) {
            int sl = w * 4 + rr, s = s0 + sl;
            float dot = 0.0f;
            #pragma unroll
            for (int j = 0; j < 32; j++) dot += Qs[sl][j] * Ks[lane][j];
            float x = (t <= s && mv) ? dot * SCALE_ : NEGV;
            lreg[rr] += __expf(x - mfin[rr]);
        }
    }
    #pragma unroll
    for (int rr = 0; rr < 4; rr++) {
        float l = lreg[rr];
        #pragma unroll
        for (int off = 16; off > 0; off >>= 1)
            l += __shfl_xor_sync(0xffffffffu, l, off);
        if (lane == 0) {
            int s = s0 + w * 4 + rr;
            g_stats[(size_t)z * S_ + s] = make_float2(mfin[rr], 1.0f / l);
        }
    }
}

// ---------------- K3: split-K partials of P @ hW1 ----------------------------
// grid (32, 8): x -> (tile, half); each CTA covers half the causal k-range.
__global__ void __launch_bounds__(256) gemm_pz2(const int* __restrict__ mask) {
    int txi = blockIdx.x;
    int tile = 15 - (txi >> 1);          // heavy tiles first
    int half = txi & 1;
    int z = blockIdx.y;
    int a = z >> 2, bb = z & 3;
    const float* Bm = g_hW1 + (size_t)a * BS_ * 128 + (size_t)bb * S_ * 128;
    float* Pout = g_part + (size_t)half * 8 * S_ * 128 + (size_t)z * S_ * 128;
    int m0 = tile * 128;
    int khalf = 64 * (tile + 1);         // (m0+128)/2, multiple of 16
    int klo = half * khalf;
    int khi = klo + khalf;

    __shared__ float QsT[32][132];
    __shared__ float Ks[2][16][33];
    __shared__ float As[16][132];
    __shared__ float Bs[2][16][128];
    __shared__ float ms[128];
    __shared__ float il[128];

    int tid = threadIdx.x;
    int tm = tid >> 4, tn = tid & 15;
    int kkA = tid & 15, mgA = (tid >> 4) * 8;
    int krow = tid >> 3, kj = (tid & 7) * 4;
    int brow = tid >> 4, bn = (tid & 15) * 8;

    {   // Q rows m0..m0+127, transposed
        int row = tid >> 1, j0 = (tid & 1) * 16;
        const float4* p = (const float4*)(g_proj + (size_t)(bb * S_ + m0 + row) * 128 + a * 64 + j0);
        float4 v0 = p[0], v1 = p[1], v2 = p[2], v3 = p[3];
        QsT[j0 + 0][row] = v0.x; QsT[j0 + 1][row] = v0.y; QsT[j0 + 2][row] = v0.z; QsT[j0 + 3][row] = v0.w;
        QsT[j0 + 4][row] = v1.x; QsT[j0 + 5][row] = v1.y; QsT[j0 + 6][row] = v1.z; QsT[j0 + 7][row] = v1.w;
        QsT[j0 + 8][row] = v2.x; QsT[j0 + 9][row] = v2.y; QsT[j0 +10][row] = v2.z; QsT[j0 +11][row] = v2.w;
        QsT[j0 +12][row] = v3.x; QsT[j0 +13][row] = v3.y; QsT[j0 +14][row] = v3.z; QsT[j0 +15][row] = v3.w;
    }
    if (tid < 128) {
        float2 st = g_stats[(size_t)z * S_ + m0 + tid];
        ms[tid] = st.x; il[tid] = st.y;
    }
    if (tid < 128) {   // initial K tile at klo
        float4 v = *(const float4*)(g_proj + (size_t)(bb * S_ + klo + krow) * 128 + a * 64 + 32 + kj);
        Ks[0][krow][kj] = v.x; Ks[0][krow][kj + 1] = v.y; Ks[0][krow][kj + 2] = v.z; Ks[0][krow][kj + 3] = v.w;
    }
    {   // initial B tile at klo
        const float4* bp = (const float4*)(Bm + (size_t)(klo + brow) * 128 + bn);
        *(float4*)&Bs[0][brow][bn]     = bp[0];
        *(float4*)&Bs[0][brow][bn + 4] = bp[1];
    }
    __syncthreads();

    ull acc2[8][4];
    #pragma unroll
    for (int i = 0; i < 8; i++)
        #pragma unroll
        for (int j = 0; j < 4; j++) acc2[i][j] = 0ULL;

    int it = 0;
    for (int k0 = klo; k0 < khi; k0 += 16, it++) {
        int buf = it & 1;
        bool hasNext = (k0 + 16) < khi;
        float4 nk, nb0, nb1;
        if (hasNext) {
            if (tid < 128)
                nk = *(const float4*)(g_proj + (size_t)(bb * S_ + k0 + 16 + krow) * 128 + a * 64 + 32 + kj);
            const float4* bp = (const float4*)(Bm + (size_t)(k0 + 16 + brow) * 128 + bn);
            nb0 = bp[0]; nb1 = bp[1];
        }
        {   // A-gen
            int t = k0 + kkA;
            int mv = mask[bb * S_ + t];
            ull av2[4] = {0ULL, 0ULL, 0ULL, 0ULL};
            #pragma unroll
            for (int j = 0; j < 32; j++) {
                ull kv = pk2(Ks[buf][kkA][j]);
                fma2(av2[0], kv, *(const ull*)&QsT[j][mgA + 0]);
                fma2(av2[1], kv, *(const ull*)&QsT[j][mgA + 2]);
                fma2(av2[2], kv, *(const ull*)&QsT[j][mgA + 4]);
                fma2(av2[3], kv, *(const ull*)&QsT[j][mgA + 6]);
            }
            #pragma unroll
            for (int i = 0; i < 4; i++) {
                float lo, hi; upk(av2[i], lo, hi);
                int mA = mgA + 2 * i;
                int sA = m0 + mA;
                float o0 = (mv && t <= sA)     ? __expf(lo * SCALE_ - ms[mA])     * il[mA]     : 0.0f;
                float o1 = (mv && t <= sA + 1) ? __expf(hi * SCALE_ - ms[mA + 1]) * il[mA + 1] : 0.0f;
                *(ull*)&As[kkA][mA] = pk(o0, o1);
            }
        }
        __syncthreads();
        #pragma unroll
        for (int kk = 0; kk < 16; kk++) {
            const ull* b64 = (const ull*)&Bs[buf][kk][tn * 8];
            ull bb0 = b64[0], bb1 = b64[1], bb2 = b64[2], bb3 = b64[3];
            float4 av0 = *(const float4*)&As[kk][tm * 8];
            float4 av1 = *(const float4*)&As[kk][tm * 8 + 4];
            ull a2_0 = pk2(av0.x), a2_1 = pk2(av0.y), a2_2 = pk2(av0.z), a2_3 = pk2(av0.w);
            ull a2_4 = pk2(av1.x), a2_5 = pk2(av1.y), a2_6 = pk2(av1.z), a2_7 = pk2(av1.w);
            fma2(acc2[0][0], a2_0, bb0); fma2(acc2[0][1], a2_0, bb1); fma2(acc2[0][2], a2_0, bb2); fma2(acc2[0][3], a2_0, bb3);
            fma2(acc2[1][0], a2_1, bb0); fma2(acc2[1][1], a2_1, bb1); fma2(acc2[1][2], a2_1, bb2); fma2(acc2[1][3], a2_1, bb3);
            fma2(acc2[2][0], a2_2, bb0); fma2(acc2[2][1], a2_2, bb1); fma2(acc2[2][2], a2_2, bb2); fma2(acc2[2][3], a2_2, bb3);
            fma2(acc2[3][0], a2_3, bb0); fma2(acc2[3][1], a2_3, bb1); fma2(acc2[3][2], a2_3, bb2); fma2(acc2[3][3], a2_3, bb3);
            fma2(acc2[4][0], a2_4, bb0); fma2(acc2[4][1], a2_4, bb1); fma2(acc2[4][2], a2_4, bb2); fma2(acc2[4][3], a2_4, bb3);
            fma2(acc2[5][0], a2_5, bb0); fma2(acc2[5][1], a2_5, bb1); fma2(acc2[5][2], a2_5, bb2); fma2(acc2[5][3], a2_5, bb3);
            fma2(acc2[6][0], a2_6, bb0); fma2(acc2[6][1], a2_6, bb1); fma2(acc2[6][2], a2_6, bb2); fma2(acc2[6][3], a2_6, bb3);
            fma2(acc2[7][0], a2_7, bb0); fma2(acc2[7][1], a2_7, bb1); fma2(acc2[7][2], a2_7, bb2); fma2(acc2[7][3], a2_7, bb3);
        }
        if (hasNext) {
            int nbuf = buf ^ 1;
            if (tid < 128) {
                Ks[nbuf][krow][kj]     = nk.x; Ks[nbuf][krow][kj + 1] = nk.y;
                Ks[nbuf][krow][kj + 2] = nk.z; Ks[nbuf][krow][kj + 3] = nk.w;
            }
            *(float4*)&Bs[nbuf][brow][bn]     = nb0;
            *(float4*)&Bs[nbuf][brow][bn + 4] = nb1;
        }
        __syncthreads();
    }

    // store raw partial (bias/gelu happen in reduce_gelu)
    #pragma unroll
    for (int i = 0; i < 8; i++) {
        int row = m0 + tm * 8 + i;
        float c0, c1, c2, c3, c4, c5, c6, c7;
        upk(acc2[i][0], c0, c1); upk(acc2[i][1], c2, c3);
        upk(acc2[i][2], c4, c5); upk(acc2[i][3], c6, c7);
        *(float4*)(Pout + (size_t)row * 128 + tn * 8)     = make_float4(c0, c1, c2, c3);
        *(float4*)(Pout + (size_t)row * 128 + tn * 8 + 4) = make_float4(c4, c5, c6, c7);
    }
}

// ---------------- K4: Y = gelu(part0 + part1 + b1) --------------------------
__global__ void __launch_bounds__(256) reduce_gelu(const float* __restrict__ b1a,
                                                   const float* __restrict__ b1b) {
    int lin4 = blockIdx.x * 256 + threadIdx.x;       // 524288 float4's
    const float4* p0 = (const float4*)g_part;
    float4 v0 = p0[lin4];
    float4 v1 = p0[lin4 + 8 * S_ * 32];              // half-1 offset in float4 units
    int n4 = lin4 & 31;
    int z  = lin4 >> 16;                             // / (S_*32)
    const float* b1 = (z >> 2) ? b1b : b1a;
    float b0 = b1[n4 * 4], bx1 = b1[n4 * 4 + 1], bx2 = b1[n4 * 4 + 2], bx3 = b1[n4 * 4 + 3];
    float4 o;
    o.x = gelu_exact(v0.x + v1.x + b0);
    o.y = gelu_exact(v0.y + v1.y + bx1);
    o.z = gelu_exact(v0.z + v1.z + bx2);
    o.w = gelu_exact(v0.w + v1.w + bx3);
    ((float4*)g_Y)[lin4] = o;
}

// ---------------- K5: logits = Y @ W2^T + b2 ; d = argmax per digit ----------
__global__ void __launch_bounds__(256) head_kernel(int which,
                                                   const float* __restrict__ W2,
                                                   const float* __restrict__ b2,
                                                   float* __restrict__ dout,
                                                   float* __restrict__ lout) {
    const float* Y = g_Y + (size_t)which * BS_ * 128;
    int r0 = blockIdx.x * 16;
    int half = blockIdx.y;
    int cbase = half * 50;
    __shared__ float ys[16][128];
    __shared__ float ws[50][128];
    __shared__ float ls[16][52];
    int tid = threadIdx.x;
    {
        int row = tid >> 4, kq = (tid & 15) * 8;
        const float4* p = (const float4*)(Y + (size_t)(r0 + row) * 128 + kq);
        *(float4*)&ys[row][kq]     = p[0];
        *(float4*)&ys[row][kq + 4] = p[1];
    }
    for (int i4 = tid; i4 < 1600; i4 += 256) {
        int c = i4 >> 5, k4 = (i4 & 31) * 4;
        *(float4*)&ws[c][k4] = *(const float4*)(W2 + (size_t)(cbase + c) * 128 + k4);
    }
    __syncthreads();

    for (int idx = tid; idx < 800; idx += 256) {
        int row = idx / 50, c = idx - row * 50;
        float acc = b2[cbase + c];
        const float4* yp = (const float4*)ys[row];
        const float4* wp = (const float4*)ws[c];
        #pragma unroll
        for (int k = 0; k < 32; k++) {
            float4 yv = yp[k], wv = wp[k];
            acc += yv.x * wv.x + yv.y * wv.y + yv.z * wv.z + yv.w * wv.w;
        }
        ls[row][c] = acc;
        lout[(size_t)(r0 + row) * 100 + cbase + c] = acc;
    }
    __syncthreads();

    if (tid < 80) {
        int row = tid / 5, dg = tid - row * 5;
        float best = ls[row][dg * 10];
        int bi = 0;
        #pragma unroll
        for (int k = 1; k < 10; k++) {
            float v = ls[row][dg * 10 + k];
            if (v > best) { best = v; bi = k; }
        }
        dout[(size_t)(r0 + row) * 10 + half * 5 + dg] = (float)bi;
    }
}

// ---------------- launch (kernel launches ONLY — graph-capture safe) ---------
extern "C" void kernel_launch(void* const* d_in, const int* in_sizes, int n_in,
                              void* d_out, int out_size) {
    const float* h    = (const float*)d_in[0];
    const int*   mask = (const int*)  d_in[1];
    const float* Wq_a = (const float*)d_in[2];
    const float* Wk_a = (const float*)d_in[3];
    const float* Wq_b = (const float*)d_in[4];
    const float* Wk_b = (const float*)d_in[5];
    const float* W1_a = (const float*)d_in[6];
    const float* b1_a = (const float*)d_in[7];
    const float* W2_a = (const float*)d_in[8];
    const float* b2_a = (const float*)d_in[9];
    const float* W1_b = (const float*)d_in[10];
    const float* b1_b = (const float*)d_in[11];
    const float* W2_b = (const float*)d_in[12];
    const float* b2_b = (const float*)d_in[13];
    float* out = (float*)d_out;

    // K0: pack attention projection weights
    pack_w<<<(128 * H_ + 255) / 256, 256>>>(Wq_a, Wk_a, Wq_b, Wk_b);
    // K1: fused h@Wcat^T, h@W1_a^T, h@W1_b^T (double-buffered 128x128)
    gemm_h128v2<<<dim3(BS_ / 128, 3), 256>>>(h, W1_a, W1_b);
    // K2: per-row softmax stats
    softmax_stats<<<dim3(S_ / 32, 8), 256>>>(mask);
    // K3: split-K partials of P @ hW1 (causal-truncated, P on the fly)
    gemm_pz2<<<dim3(32, 8), 256>>>(mask);
    // K4: combine halves + bias + gelu -> g_Y
    reduce_gelu<<<2048, 256>>>(b1_a, b1_b);
    // K5: logits + STE argmax.  Output layout: [d_a | d_b | logits_a | logits_b]
    head_kernel<<<dim3(512, 2), 256>>>(0, W2_a, b2_a, out,         out + 163840);
    head_kernel<<<dim3(512, 2), 256>>>(1, W2_b, b2_b, out + 81920, out + 983040);
}